// round 9
// baseline (speedup 1.0000x reference)
#include <cuda_runtime.h>
#include <cuda_fp16.h>
#include <cstdint>

#define N_NODES 100000
#define E_EDGES 3200000
#define F_IN_D  512
#define H_DIM   256

// ---- scratch (device globals; no allocation allowed) ----
__device__ int    g_is64;
__device__ int    g_src [E_EDGES];
__device__ int    g_dst [E_EDGES];
__device__ int    g_degi[N_NODES];
__device__ int    g_off [N_NODES + 1];
__device__ int    g_cur [N_NODES];
__device__ int    g_csr [E_EDGES];
__device__ float  g_dinv[N_NODES];
__device__ __align__(16) __half g_gbuf[(size_t)N_NODES * H_DIM];  // fp16: x@W1 (unscaled)
__device__ float  g_t   [N_NODES];

// ---- streams/events created at program load ----
static cudaStream_t s_side = 0;
static cudaEvent_t  ev_fork = 0, ev_join = 0;
static int s_ok = 0;
namespace {
struct StreamInit {
    StreamInit() {
        if (cudaStreamCreateWithFlags(&s_side, cudaStreamNonBlocking) == cudaSuccess &&
            cudaEventCreateWithFlags(&ev_fork, cudaEventDisableTiming) == cudaSuccess &&
            cudaEventCreateWithFlags(&ev_join, cudaEventDisableTiming) == cudaSuccess)
            s_ok = 1;
    }
} s_init;
}

// ---- fused: zero degree histogram + dtype probe ----
__global__ void k_zero_detect(const int* __restrict__ ei32) {
    int i = blockIdx.x * blockDim.x + threadIdx.x;
    if (i == 0) g_is64 = 1;                      // overwritten below if int32
    if (i < N_NODES) g_degi[i] = 0;
    if (i < 4096) {
        if (ei32[2 * i + 1] != 0) g_is64 = 0;    // benign 1->0 race (join before k_prep)
    }
}

// ---- fused convert + degree count ----
__global__ void k_prep(const void* __restrict__ ei) {
    int e = blockIdx.x * blockDim.x + threadIdx.x;
    if (e >= E_EDGES) return;
    int s, d;
    if (g_is64) {
        const long long* p = (const long long*)ei;
        s = (int)p[e];
        d = (int)p[E_EDGES + e];
    } else {
        const int* p = (const int*)ei;
        s = p[e];
        d = p[E_EDGES + e];
    }
    g_src[e] = s;
    g_dst[e] = d;
    atomicAdd(&g_degi[d], 1);
}

// ---- single-block scan: g_off / g_cur / g_dinv from g_degi ----
__global__ __launch_bounds__(1024) void k_scan() {
    __shared__ int wsum[32];
    __shared__ int carry_s;
    const int tid = threadIdx.x, lane = tid & 31, wid = tid >> 5;
    if (tid == 0) carry_s = 0;
    __syncthreads();
    for (int base = 0; base < N_NODES; base += 1024) {
        int i = base + tid;
        int v = (i < N_NODES) ? g_degi[i] : 0;
        int inc = v;
#pragma unroll
        for (int o = 1; o < 32; o <<= 1) {
            int t = __shfl_up_sync(0xffffffffu, inc, o);
            if (lane >= o) inc += t;
        }
        if (lane == 31) wsum[wid] = inc;
        __syncthreads();
        if (wid == 0) {
            int w = wsum[lane];
#pragma unroll
            for (int o = 1; o < 32; o <<= 1) {
                int t = __shfl_up_sync(0xffffffffu, w, o);
                if (lane >= o) w += t;
            }
            wsum[lane] = w;
        }
        __syncthreads();
        int wpre  = (wid > 0) ? wsum[wid - 1] : 0;
        int total = wsum[31];
        int carry = carry_s;
        if (i < N_NODES) {
            int excl = carry + wpre + inc - v;
            g_cur[i]     = excl;
            g_off[i + 1] = excl + v;
            g_dinv[i]    = rsqrtf((float)v + 1.0f);   // fused dinv
        }
        __syncthreads();
        if (tid == 0) carry_s = carry + total;
        __syncthreads();
    }
    if (tid == 0) g_off[0] = 0;
}

__global__ void k_fill_csr() {
    int e = blockIdx.x * blockDim.x + threadIdx.x;
    if (e >= E_EDGES) return;
    int slot = atomicAdd(&g_cur[g_dst[e]], 1);
    g_csr[slot] = g_src[e];
}

// ------- tf32 MMA GEMM1: CTA tile 128x256 (full H), warp tile 64x64 -------
#define A_PITCH 36    // (4g+qc) mod 32 distinct -> conflict-free
#define B_PITCH 264   // 264 mod 32 = 8 -> (8qc+g) distinct -> conflict-free
#define A_STG  (128 * A_PITCH)
#define B_STG  (32 * B_PITCH)
#define N_STAGE 3
#define GEMM_SMEM_BYTES (N_STAGE * (A_STG + B_STG) * 4)

__device__ __forceinline__ void cp16(uint32_t smem_addr, const void* gsrc, int src_bytes) {
    asm volatile("cp.async.cg.shared.global [%0], [%1], 16, %2;"
                 :: "r"(smem_addr), "l"(gsrc), "r"(src_bytes));
}

__global__ __launch_bounds__(256, 1) void k_gemm1(const float* __restrict__ x,
                                                  const float* __restrict__ W1) {
    extern __shared__ float smem[];
    float* As = smem;                       // [N_STAGE][A_STG]
    float* Bs = smem + N_STAGE * A_STG;     // [N_STAGE][B_STG]

    const int tid  = threadIdx.x;
    const int lane = tid & 31;
    const int warp = tid >> 5;
    const int wm   = warp & 1;    // 2 warps in M (64 rows each)
    const int wn   = warp >> 1;   // 4 warps in N (64 cols each)
    const int g    = lane >> 2;   // 0..7
    const int qc   = lane & 3;    // 0..3
    const int bm0  = blockIdx.x * 128;

    const uint32_t as_u32 = (uint32_t)__cvta_generic_to_shared(As);
    const uint32_t bs_u32 = (uint32_t)__cvta_generic_to_shared(Bs);

    float acc[4][8][4];
#pragma unroll
    for (int mt = 0; mt < 4; mt++)
#pragma unroll
        for (int nt = 0; nt < 8; nt++)
#pragma unroll
            for (int i = 0; i < 4; i++) acc[mt][nt][i] = 0.0f;

    auto load_tiles = [&](int k0, int buf) {
        // A tile: 128 rows x 32 k = 1024 float4 (4/thread)
#pragma unroll
        for (int i = 0; i < 4; i++) {
            int idx = tid + i * 256;
            int row = idx >> 3;
            int col = (idx & 7) * 4;
            int grow = bm0 + row;
            int ok = (grow < N_NODES);
            const float* src = &x[(size_t)(ok ? grow : 0) * F_IN_D + k0 + col];
            cp16(as_u32 + (buf * A_STG + row * A_PITCH + col) * 4, src, ok ? 16 : 0);
        }
        // B tile: 32 k x 256 n = 2048 float4 (8/thread)
#pragma unroll
        for (int i = 0; i < 8; i++) {
            int idx = tid + i * 256;
            int row = idx >> 6;
            int col = (idx & 63) * 4;
            cp16(bs_u32 + (buf * B_STG + row * B_PITCH + col) * 4,
                 &W1[(size_t)(k0 + row) * H_DIM + col], 16);
        }
        asm volatile("cp.async.commit_group;");
    };

    load_tiles(0, 0);
    load_tiles(32, 1);

    for (int k0 = 0, it = 0; k0 < F_IN_D; k0 += 32, it++) {
        int s = it % N_STAGE;
        if (k0 + 32 < F_IN_D)
            asm volatile("cp.async.wait_group 1;");
        else
            asm volatile("cp.async.wait_group 0;");
        __syncthreads();

        const float* A = As + s * A_STG;
        const float* B = Bs + s * B_STG;
#pragma unroll
        for (int kk = 0; kk < 32; kk += 8) {
            uint32_t a[4][4];
#pragma unroll
            for (int mt = 0; mt < 4; mt++) {
                int r0 = wm * 64 + mt * 16 + g;
                const float* pa = &A[r0 * A_PITCH + kk + qc];
                a[mt][0] = __float_as_uint(pa[0]);
                a[mt][1] = __float_as_uint(pa[8 * A_PITCH]);
                a[mt][2] = __float_as_uint(pa[4]);
                a[mt][3] = __float_as_uint(pa[8 * A_PITCH + 4]);
            }
#pragma unroll
            for (int nt = 0; nt < 8; nt++) {
                int c0 = wn * 64 + nt * 8 + g;
                uint32_t b0 = __float_as_uint(B[(kk + qc) * B_PITCH + c0]);
                uint32_t b1 = __float_as_uint(B[(kk + qc + 4) * B_PITCH + c0]);
#pragma unroll
                for (int mt = 0; mt < 4; mt++) {
                    asm volatile(
                        "mma.sync.aligned.m16n8k8.row.col.f32.tf32.tf32.f32 "
                        "{%0,%1,%2,%3}, {%4,%5,%6,%7}, {%8,%9}, {%0,%1,%2,%3};"
                        : "+f"(acc[mt][nt][0]), "+f"(acc[mt][nt][1]),
                          "+f"(acc[mt][nt][2]), "+f"(acc[mt][nt][3])
                        : "r"(a[mt][0]), "r"(a[mt][1]), "r"(a[mt][2]), "r"(a[mt][3]),
                          "r"(b0), "r"(b1));
                }
            }
        }
        int kn = k0 + 64;
        if (kn < F_IN_D) load_tiles(kn, (it + 2) % N_STAGE);
    }

    // epilogue: store raw h as fp16 (dinv applied in k_fuse)
#pragma unroll
    for (int mt = 0; mt < 4; mt++) {
        int row0 = bm0 + wm * 64 + mt * 16 + g;
        int row1 = row0 + 8;
#pragma unroll
        for (int nt = 0; nt < 8; nt++) {
            int col = wn * 64 + nt * 8 + qc * 2;
            if (row0 < N_NODES)
                *(__half2*)&g_gbuf[(size_t)row0 * H_DIM + col] =
                    __floats2half2_rn(acc[mt][nt][0], acc[mt][nt][1]);
            if (row1 < N_NODES)
                *(__half2*)&g_gbuf[(size_t)row1 * H_DIM + col] =
                    __floats2half2_rn(acc[mt][nt][2], acc[mt][nt][3]);
        }
    }
}

// ---- fused layer-1 aggregation + ReLU + layer-2 matvec: one warp per node ----
__global__ __launch_bounds__(256) void k_fuse(const float* __restrict__ b1,
                                              const float* __restrict__ W2) {
    int gw   = (blockIdx.x * blockDim.x + threadIdx.x) >> 5;
    int lane = threadIdx.x & 31;
    if (gw >= N_NODES) return;

    float a[8];
#pragma unroll
    for (int i = 0; i < 8; i++) a[i] = 0.0f;

    auto add_row = [&](uint4 v, float sc) {
        const __half2* h = (const __half2*)&v;
#pragma unroll
        for (int i = 0; i < 4; i++) {
            float2 f = __half22float2(h[i]);
            a[2 * i]     = fmaf(sc, f.x, a[2 * i]);
            a[2 * i + 1] = fmaf(sc, f.y, a[2 * i + 1]);
        }
    };

    const float dv = g_dinv[gw];
    add_row(((const uint4*)(g_gbuf + (size_t)gw * H_DIM))[lane], dv);  // self-loop

    const int beg = g_off[gw];
    const int end = g_off[gw + 1];
    for (int j = beg; j < end; ++j) {
        int src = g_csr[j];
        add_row(((const uint4*)(g_gbuf + (size_t)src * H_DIM))[lane], g_dinv[src]);
    }

    int c = lane * 8;
    float4 bb0 = *(const float4*)&b1[c];
    float4 bb1 = *(const float4*)&b1[c + 4];
    float4 w0  = *(const float4*)&W2[c];
    float4 w1  = *(const float4*)&W2[c + 4];

    float s = 0.0f;
    s += fmaxf(fmaf(dv, a[0], bb0.x), 0.f) * w0.x;
    s += fmaxf(fmaf(dv, a[1], bb0.y), 0.f) * w0.y;
    s += fmaxf(fmaf(dv, a[2], bb0.z), 0.f) * w0.z;
    s += fmaxf(fmaf(dv, a[3], bb0.w), 0.f) * w0.w;
    s += fmaxf(fmaf(dv, a[4], bb1.x), 0.f) * w1.x;
    s += fmaxf(fmaf(dv, a[5], bb1.y), 0.f) * w1.y;
    s += fmaxf(fmaf(dv, a[6], bb1.z), 0.f) * w1.z;
    s += fmaxf(fmaf(dv, a[7], bb1.w), 0.f) * w1.w;

#pragma unroll
    for (int o = 16; o > 0; o >>= 1) s += __shfl_down_sync(0xffffffffu, s, o);
    if (lane == 0) g_t[gw] = dv * s;
}

// ---- layer-2 aggregation ----
__global__ __launch_bounds__(256) void k_agg2(const float* __restrict__ b2,
                                              float* __restrict__ out) {
    int gw   = (blockIdx.x * blockDim.x + threadIdx.x) >> 5;
    int lane = threadIdx.x & 31;
    if (gw >= N_NODES) return;
    const int beg = g_off[gw];
    const int end = g_off[gw + 1];
    float s = (lane == 0) ? g_t[gw] : 0.0f;
    for (int j = beg + lane; j < end; j += 32) s += g_t[g_csr[j]];
#pragma unroll
    for (int o = 16; o > 0; o >>= 1) s += __shfl_down_sync(0xffffffffu, s, o);
    if (lane == 0) out[gw] = fmaf(g_dinv[gw], s, b2[0]);
}

// ---------------- launch ----------------
extern "C" void kernel_launch(void* const* d_in, const int* in_sizes, int n_in,
                              void* d_out, int out_size) {
    const float* x   = (const float*)d_in[0];
    const void*  ei  = d_in[1];
    const float* W1  = (const float*)d_in[2];
    const float* b1  = (const float*)d_in[3];
    const float* W2  = (const float*)d_in[4];
    const float* b2  = (const float*)d_in[5];
    float*       out = (float*)d_out;

    (void)in_sizes; (void)n_in; (void)out_size;

    static int attr_set = 0;
    if (!attr_set) {
        cudaFuncSetAttribute(k_gemm1, cudaFuncAttributeMaxDynamicSharedMemorySize,
                             GEMM_SMEM_BYTES);
        attr_set = 1;
    }

    const int TB = 256;
    const int nb_nodes = (N_NODES + TB - 1) / TB;
    const int nb_edges = (E_EDGES + TB - 1) / TB;
    dim3 ggrid((N_NODES + 127) / 128, 1);

    if (s_ok) {
        cudaEventRecord(ev_fork, 0);
        cudaStreamWaitEvent(s_side, ev_fork, 0);
        k_gemm1<<<ggrid, 256, GEMM_SMEM_BYTES, s_side>>>(x, W1);
        cudaEventRecord(ev_join, s_side);

        k_zero_detect<<<nb_nodes, TB>>>((const int*)ei);
        k_prep<<<nb_edges, TB>>>(ei);
        k_scan<<<1, 1024>>>();
        k_fill_csr<<<nb_edges, TB>>>();

        cudaStreamWaitEvent(0, ev_join, 0);
    } else {
        k_zero_detect<<<nb_nodes, TB>>>((const int*)ei);
        k_prep<<<nb_edges, TB>>>(ei);
        k_scan<<<1, 1024>>>();
        k_fill_csr<<<nb_edges, TB>>>();
        k_gemm1<<<ggrid, 256, GEMM_SMEM_BYTES>>>(x, W1);
    }

    int warps_blocks = (N_NODES * 32 + TB - 1) / TB;
    k_fuse<<<warps_blocks, TB>>>(b1, W2);
    k_agg2<<<warps_blocks, TB>>>(b2, out);
}

// round 10
// speedup vs baseline: 1.2070x; 1.2070x over previous
#include <cuda_runtime.h>
#include <cuda_fp16.h>
#include <cstdint>

#define N_NODES 100000
#define E_EDGES 3200000
#define F_IN_D  512
#define H_DIM   256
#define SCAN_BLKS ((N_NODES + 1023) / 1024)   // 98

// ---- scratch (device globals; no allocation allowed) ----
__device__ int    g_is64;
__device__ int    g_src [E_EDGES];
__device__ int    g_dst [E_EDGES];
__device__ int    g_degi[N_NODES];
__device__ int    g_off [N_NODES + 1];
__device__ int    g_cur [N_NODES];
__device__ int    g_incl[N_NODES];        // per-block inclusive scan temp
__device__ int    g_bsum[SCAN_BLKS];      // per-block totals -> exclusive offsets
__device__ int    g_csr [E_EDGES];
__device__ float  g_dinv[N_NODES];
__device__ __align__(16) __half g_gbuf[(size_t)N_NODES * H_DIM];  // fp16: x@W1 (unscaled)
__device__ float  g_t   [N_NODES];

// ---- streams/events created at program load ----
static cudaStream_t s_side = 0;
static cudaEvent_t  ev_fork = 0, ev_join = 0;
static int s_ok = 0;
namespace {
struct StreamInit {
    StreamInit() {
        if (cudaStreamCreateWithFlags(&s_side, cudaStreamNonBlocking) == cudaSuccess &&
            cudaEventCreateWithFlags(&ev_fork, cudaEventDisableTiming) == cudaSuccess &&
            cudaEventCreateWithFlags(&ev_join, cudaEventDisableTiming) == cudaSuccess)
            s_ok = 1;
    }
} s_init;
}

// ---- fused: zero degree histogram + dtype probe ----
__global__ void k_zero_detect(const int* __restrict__ ei32) {
    int i = blockIdx.x * blockDim.x + threadIdx.x;
    if (i == 0) g_is64 = 1;
    if (i < N_NODES) g_degi[i] = 0;
    if (i < 4096) {
        if (ei32[2 * i + 1] != 0) g_is64 = 0;    // benign 1->0 race
    }
}

// ---- fused convert + degree count ----
__global__ void k_prep(const void* __restrict__ ei) {
    int e = blockIdx.x * blockDim.x + threadIdx.x;
    if (e >= E_EDGES) return;
    int s, d;
    if (g_is64) {
        const long long* p = (const long long*)ei;
        s = (int)p[e];
        d = (int)p[E_EDGES + e];
    } else {
        const int* p = (const int*)ei;
        s = p[e];
        d = p[E_EDGES + e];
    }
    g_src[e] = s;
    g_dst[e] = d;
    atomicAdd(&g_degi[d], 1);
}

// ---- multi-block scan, pass 1: per-block inclusive scan + block totals ----
__global__ __launch_bounds__(1024) void k_scan1() {
    __shared__ int wsum[32];
    const int tid = threadIdx.x, lane = tid & 31, wid = tid >> 5;
    int i = blockIdx.x * 1024 + tid;
    int v = (i < N_NODES) ? g_degi[i] : 0;
    int inc = v;
#pragma unroll
    for (int o = 1; o < 32; o <<= 1) {
        int t = __shfl_up_sync(0xffffffffu, inc, o);
        if (lane >= o) inc += t;
    }
    if (lane == 31) wsum[wid] = inc;
    __syncthreads();
    if (wid == 0) {
        int w = wsum[lane];
#pragma unroll
        for (int o = 1; o < 32; o <<= 1) {
            int t = __shfl_up_sync(0xffffffffu, w, o);
            if (lane >= o) w += t;
        }
        wsum[lane] = w;
    }
    __syncthreads();
    int wpre = (wid > 0) ? wsum[wid - 1] : 0;
    if (i < N_NODES) g_incl[i] = wpre + inc;
    if (tid == 1023) g_bsum[blockIdx.x] = wpre + inc;
}

// ---- pass 2: single block scans the block totals (exclusive) ----
__global__ __launch_bounds__(128) void k_scan2() {
    __shared__ int wsum[4];
    const int tid = threadIdx.x, lane = tid & 31, wid = tid >> 5;
    int v = (tid < SCAN_BLKS) ? g_bsum[tid] : 0;
    int inc = v;
#pragma unroll
    for (int o = 1; o < 32; o <<= 1) {
        int t = __shfl_up_sync(0xffffffffu, inc, o);
        if (lane >= o) inc += t;
    }
    if (lane == 31) wsum[wid] = inc;
    __syncthreads();
    int wpre = 0;
    for (int w = 0; w < wid; w++) wpre += wsum[w];
    if (tid < SCAN_BLKS) g_bsum[tid] = wpre + inc - v;  // exclusive
}

// ---- pass 3: combine + emit g_off / g_cur / g_dinv ----
__global__ void k_scan3() {
    int i = blockIdx.x * blockDim.x + threadIdx.x;
    if (i >= N_NODES) return;
    int v    = g_degi[i];
    int incl = g_bsum[i >> 10] + g_incl[i];
    g_off[i + 1] = incl;
    g_cur[i]     = incl - v;
    g_dinv[i]    = rsqrtf((float)v + 1.0f);
    if (i == 0) g_off[0] = 0;
}

__global__ void k_fill_csr() {
    int e = blockIdx.x * blockDim.x + threadIdx.x;
    if (e >= E_EDGES) return;
    int slot = atomicAdd(&g_cur[g_dst[e]], 1);
    g_csr[slot] = g_src[e];
}

// ------- tf32 MMA GEMM1, 3-stage cp.async pipeline, 128x128 tile -------
#define A_PITCH 36
#define B_PITCH 136
#define A_STG  (128 * A_PITCH)
#define B_STG  (32 * B_PITCH)
#define N_STAGE 3
#define GEMM_SMEM_BYTES (N_STAGE * (A_STG + B_STG) * 4)

__device__ __forceinline__ void cp16(uint32_t smem_addr, const void* gsrc, int src_bytes) {
    asm volatile("cp.async.cg.shared.global [%0], [%1], 16, %2;"
                 :: "r"(smem_addr), "l"(gsrc), "r"(src_bytes));
}

__global__ __launch_bounds__(256) void k_gemm1(const float* __restrict__ x,
                                               const float* __restrict__ W1) {
    extern __shared__ float smem[];
    float* As = smem;
    float* Bs = smem + N_STAGE * A_STG;

    const int tid  = threadIdx.x;
    const int lane = tid & 31;
    const int warp = tid >> 5;
    const int wm   = warp & 3;
    const int wn   = warp >> 2;
    const int g    = lane >> 2;
    const int qc   = lane & 3;
    const int bm0  = blockIdx.x * 128;
    const int bn0  = blockIdx.y * 128;

    const uint32_t as_u32 = (uint32_t)__cvta_generic_to_shared(As);
    const uint32_t bs_u32 = (uint32_t)__cvta_generic_to_shared(Bs);

    float acc[2][8][4];
#pragma unroll
    for (int mt = 0; mt < 2; mt++)
#pragma unroll
        for (int nt = 0; nt < 8; nt++)
#pragma unroll
            for (int i = 0; i < 4; i++) acc[mt][nt][i] = 0.0f;

    auto load_tiles = [&](int k0, int buf) {
#pragma unroll
        for (int i = 0; i < 4; i++) {
            int idx = tid + i * 256;
            int row = idx >> 3;
            int col = (idx & 7) * 4;
            int grow = bm0 + row;
            int ok = (grow < N_NODES);
            const float* src = &x[(size_t)(ok ? grow : 0) * F_IN_D + k0 + col];
            cp16(as_u32 + (buf * A_STG + row * A_PITCH + col) * 4, src, ok ? 16 : 0);
        }
#pragma unroll
        for (int i = 0; i < 4; i++) {
            int idx = tid + i * 256;
            int row = idx >> 5;
            int col = (idx & 31) * 4;
            cp16(bs_u32 + (buf * B_STG + row * B_PITCH + col) * 4,
                 &W1[(size_t)(k0 + row) * H_DIM + bn0 + col], 16);
        }
        asm volatile("cp.async.commit_group;");
    };

    load_tiles(0, 0);
    load_tiles(32, 1);

    for (int k0 = 0, it = 0; k0 < F_IN_D; k0 += 32, it++) {
        int s = it % N_STAGE;
        if (k0 + 32 < F_IN_D)
            asm volatile("cp.async.wait_group 1;");
        else
            asm volatile("cp.async.wait_group 0;");
        __syncthreads();

        const float* A = As + s * A_STG;
        const float* B = Bs + s * B_STG;
#pragma unroll
        for (int kk = 0; kk < 32; kk += 8) {
            uint32_t a[2][4];
#pragma unroll
            for (int mt = 0; mt < 2; mt++) {
                int r0 = wm * 32 + mt * 16 + g;
                const float* pa = &A[r0 * A_PITCH + kk + qc];
                a[mt][0] = __float_as_uint(pa[0]);
                a[mt][1] = __float_as_uint(pa[8 * A_PITCH]);
                a[mt][2] = __float_as_uint(pa[4]);
                a[mt][3] = __float_as_uint(pa[8 * A_PITCH + 4]);
            }
#pragma unroll
            for (int nt = 0; nt < 8; nt++) {
                int c0 = wn * 64 + nt * 8 + g;
                uint32_t b0 = __float_as_uint(B[(kk + qc) * B_PITCH + c0]);
                uint32_t b1 = __float_as_uint(B[(kk + qc + 4) * B_PITCH + c0]);
#pragma unroll
                for (int mt = 0; mt < 2; mt++) {
                    asm volatile(
                        "mma.sync.aligned.m16n8k8.row.col.f32.tf32.tf32.f32 "
                        "{%0,%1,%2,%3}, {%4,%5,%6,%7}, {%8,%9}, {%0,%1,%2,%3};"
                        : "+f"(acc[mt][nt][0]), "+f"(acc[mt][nt][1]),
                          "+f"(acc[mt][nt][2]), "+f"(acc[mt][nt][3])
                        : "r"(a[mt][0]), "r"(a[mt][1]), "r"(a[mt][2]), "r"(a[mt][3]),
                          "r"(b0), "r"(b1));
                }
            }
        }
        int kn = k0 + 64;
        if (kn < F_IN_D) load_tiles(kn, (it + 2) % N_STAGE);
    }

    // epilogue: store raw h as fp16 (dinv applied in k_fuse)
#pragma unroll
    for (int mt = 0; mt < 2; mt++) {
        int row0 = bm0 + wm * 32 + mt * 16 + g;
        int row1 = row0 + 8;
#pragma unroll
        for (int nt = 0; nt < 8; nt++) {
            int col = bn0 + wn * 64 + nt * 8 + qc * 2;
            if (row0 < N_NODES)
                *(__half2*)&g_gbuf[(size_t)row0 * H_DIM + col] =
                    __floats2half2_rn(acc[mt][nt][0], acc[mt][nt][1]);
            if (row1 < N_NODES)
                *(__half2*)&g_gbuf[(size_t)row1 * H_DIM + col] =
                    __floats2half2_rn(acc[mt][nt][2], acc[mt][nt][3]);
        }
    }
}

// ---- fused layer-1 aggregation + ReLU + layer-2 matvec: one warp per node ----
__global__ __launch_bounds__(256) void k_fuse(const float* __restrict__ b1,
                                              const float* __restrict__ W2) {
    int gw   = (blockIdx.x * blockDim.x + threadIdx.x) >> 5;
    int lane = threadIdx.x & 31;
    if (gw >= N_NODES) return;

    float a[8];
#pragma unroll
    for (int i = 0; i < 8; i++) a[i] = 0.0f;

    auto add_row = [&](uint4 v, float sc) {
        const __half2* h = (const __half2*)&v;
#pragma unroll
        for (int i = 0; i < 4; i++) {
            float2 f = __half22float2(h[i]);
            a[2 * i]     = fmaf(sc, f.x, a[2 * i]);
            a[2 * i + 1] = fmaf(sc, f.y, a[2 * i + 1]);
        }
    };

    const float dv = g_dinv[gw];
    add_row(((const uint4*)(g_gbuf + (size_t)gw * H_DIM))[lane], dv);  // self-loop

    const int beg = g_off[gw];
    const int end = g_off[gw + 1];
    for (int j = beg; j < end; ++j) {
        int src = g_csr[j];
        add_row(((const uint4*)(g_gbuf + (size_t)src * H_DIM))[lane], g_dinv[src]);
    }

    int c = lane * 8;
    float4 bb0 = *(const float4*)&b1[c];
    float4 bb1 = *(const float4*)&b1[c + 4];
    float4 w0  = *(const float4*)&W2[c];
    float4 w1  = *(const float4*)&W2[c + 4];

    float s = 0.0f;
    s += fmaxf(fmaf(dv, a[0], bb0.x), 0.f) * w0.x;
    s += fmaxf(fmaf(dv, a[1], bb0.y), 0.f) * w0.y;
    s += fmaxf(fmaf(dv, a[2], bb0.z), 0.f) * w0.z;
    s += fmaxf(fmaf(dv, a[3], bb0.w), 0.f) * w0.w;
    s += fmaxf(fmaf(dv, a[4], bb1.x), 0.f) * w1.x;
    s += fmaxf(fmaf(dv, a[5], bb1.y), 0.f) * w1.y;
    s += fmaxf(fmaf(dv, a[6], bb1.z), 0.f) * w1.z;
    s += fmaxf(fmaf(dv, a[7], bb1.w), 0.f) * w1.w;

#pragma unroll
    for (int o = 16; o > 0; o >>= 1) s += __shfl_down_sync(0xffffffffu, s, o);
    if (lane == 0) g_t[gw] = dv * s;
}

// ---- layer-2 aggregation ----
__global__ __launch_bounds__(256) void k_agg2(const float* __restrict__ b2,
                                              float* __restrict__ out) {
    int gw   = (blockIdx.x * blockDim.x + threadIdx.x) >> 5;
    int lane = threadIdx.x & 31;
    if (gw >= N_NODES) return;
    const int beg = g_off[gw];
    const int end = g_off[gw + 1];
    float s = (lane == 0) ? g_t[gw] : 0.0f;
    for (int j = beg + lane; j < end; j += 32) s += g_t[g_csr[j]];
#pragma unroll
    for (int o = 16; o > 0; o >>= 1) s += __shfl_down_sync(0xffffffffu, s, o);
    if (lane == 0) out[gw] = fmaf(g_dinv[gw], s, b2[0]);
}

// ---------------- launch ----------------
extern "C" void kernel_launch(void* const* d_in, const int* in_sizes, int n_in,
                              void* d_out, int out_size) {
    const float* x   = (const float*)d_in[0];
    const void*  ei  = d_in[1];
    const float* W1  = (const float*)d_in[2];
    const float* b1  = (const float*)d_in[3];
    const float* W2  = (const float*)d_in[4];
    const float* b2  = (const float*)d_in[5];
    float*       out = (float*)d_out;

    (void)in_sizes; (void)n_in; (void)out_size;

    static int attr_set = 0;
    if (!attr_set) {
        cudaFuncSetAttribute(k_gemm1, cudaFuncAttributeMaxDynamicSharedMemorySize,
                             GEMM_SMEM_BYTES);
        attr_set = 1;
    }

    const int TB = 256;
    const int nb_nodes = (N_NODES + TB - 1) / TB;
    const int nb_edges = (E_EDGES + TB - 1) / TB;
    dim3 ggrid((N_NODES + 127) / 128, H_DIM / 128);

    if (s_ok) {
        cudaEventRecord(ev_fork, 0);
        cudaStreamWaitEvent(s_side, ev_fork, 0);
        k_gemm1<<<ggrid, 256, GEMM_SMEM_BYTES, s_side>>>(x, W1);
        cudaEventRecord(ev_join, s_side);

        k_zero_detect<<<nb_nodes, TB>>>((const int*)ei);
        k_prep<<<nb_edges, TB>>>(ei);
        k_scan1<<<SCAN_BLKS, 1024>>>();
        k_scan2<<<1, 128>>>();
        k_scan3<<<nb_nodes, TB>>>();
        k_fill_csr<<<nb_edges, TB>>>();

        cudaStreamWaitEvent(0, ev_join, 0);
    } else {
        k_zero_detect<<<nb_nodes, TB>>>((const int*)ei);
        k_prep<<<nb_edges, TB>>>(ei);
        k_scan1<<<SCAN_BLKS, 1024>>>();
        k_scan2<<<1, 128>>>();
        k_scan3<<<nb_nodes, TB>>>();
        k_fill_csr<<<nb_edges, TB>>>();
        k_gemm1<<<ggrid, 256, GEMM_SMEM_BYTES>>>(x, W1);
    }

    int warps_blocks = (N_NODES * 32 + TB - 1) / TB;
    k_fuse<<<warps_blocks, TB>>>(b1, W2);
    k_agg2<<<warps_blocks, TB>>>(b2, out);
}